// round 10
// baseline (speedup 1.0000x reference)
#include <cuda_runtime.h>
#include <cuda_fp16.h>
#include <cstdint>

#define C_DIM   256
#define HGT     192
#define WID     192
#define HW      (HGT*WID)
#define CHW     (C_DIM*HW)
#define BATCH   2
#define NWIN    12
#define WINS_B  (NWIN*NWIN)
#define NWINS   (BATCH*WINS_B)      // 288
#define HEADS   8
#define HD      32
#define S_TOK   256
#define NWH     (NWINS*HEADS)       // 2304
#define SCALE_F 0.17677669529663688f

// ---------------- scratch (fp16 intermediates) -------------------------------
__device__ __half g_qh[(size_t)NWH * S_TOK * HD];         // [wh][s][d]
__device__ __half g_kh[(size_t)NWH * S_TOK * HD];         // [wh][t][d]
__device__ __half g_vh[(size_t)NWH * HD * S_TOK];         // [wh][d][t]
__device__ __half g_attnh[(size_t)NWINS * S_TOK * C_DIM]; // [win][s][c]
__device__ __half g_wh[4 * C_DIM * C_DIM];                // Wq,Wk,Wv,Wo fp16
__device__ float  g_bkv[2 * C_DIM];                       // bk ++ bv
__device__ __half g_xth[(size_t)2 * BATCH * WINS_B * S_TOK * C_DIM]; // [img][b][win][s][c]

// ---------------- helpers ----------------------------------------------------
__device__ __forceinline__ void mma_f16(float c[4],
                                        const uint32_t a[4],
                                        const uint32_t b[2]) {
    asm volatile(
        "mma.sync.aligned.m16n8k16.row.col.f32.f16.f16.f32 "
        "{%0,%1,%2,%3},{%4,%5,%6,%7},{%8,%9},{%0,%1,%2,%3};"
        : "+f"(c[0]), "+f"(c[1]), "+f"(c[2]), "+f"(c[3])
        : "r"(a[0]), "r"(a[1]), "r"(a[2]), "r"(a[3]),
          "r"(b[0]), "r"(b[1]));
}

__device__ __forceinline__ void cp_async16(void* smem, const void* gmem) {
    unsigned sa = (unsigned)__cvta_generic_to_shared(smem);
    asm volatile("cp.async.cg.shared.global [%0], [%1], 16;" :: "r"(sa), "l"(gmem));
}
__device__ __forceinline__ void cp_commit() {
    asm volatile("cp.async.commit_group;");
}
template<int N> __device__ __forceinline__ void cp_wait() {
    asm volatile("cp.async.wait_group %0;" :: "n"(N));
}
__device__ __forceinline__ uint32_t ldu32(const __half* p) {
    return *reinterpret_cast<const uint32_t*>(p);
}
__device__ __forceinline__ uint32_t h2u(__half2 h) {
    return *reinterpret_cast<uint32_t*>(&h);
}

// ---------------- weight + bias conversion -----------------------------------
__global__ void conv_w_kernel(const float* __restrict__ Wq,
                              const float* __restrict__ Wk,
                              const float* __restrict__ Wv,
                              const float* __restrict__ Wo,
                              const float* __restrict__ bk,
                              const float* __restrict__ bv)
{
    int i = blockIdx.x * blockDim.x + threadIdx.x;
    if (i < C_DIM * C_DIM) {
        g_wh[                 i] = __float2half_rn(Wq[i]);
        g_wh[  C_DIM*C_DIM + i] = __float2half_rn(Wk[i]);
        g_wh[2*C_DIM*C_DIM + i] = __float2half_rn(Wv[i]);
        g_wh[3*C_DIM*C_DIM + i] = __float2half_rn(Wo[i]);
    }
    if (i < C_DIM) {
        g_bkv[i]         = bk[i];
        g_bkv[C_DIM + i] = bv[i];
    }
}

// ---------------- x convert + windowize (streaming) --------------------------
// [c][h][w] fp32 -> [img][b][win][s][c] fp16. One 32-channel slab per block.
__global__ __launch_bounds__(256)
void conv_x_kernel(const float* __restrict__ x_q,
                   const float* __restrict__ x_kv)
{
    __shared__ float ts[32][257];

    const int wi  = blockIdx.x;           // 0..143
    const int b   = blockIdx.y;           // 0..1
    const int z   = blockIdx.z;           // img*8 + cc
    const int img = z >> 3;
    const int cc  = z & 7;
    const int tid = threadIdx.x;

    const float* src = (img ? x_kv : x_q) + (size_t)b * CHW + (size_t)cc * 32 * HW;
    __half* dst = g_xth + ((size_t)img * BATCH * WINS_B
                         + (size_t)b * WINS_B + wi) * (S_TOK * C_DIM) + cc * 32;

    const int h0 = (wi / NWIN) * 16;
    const int w0 = (wi % NWIN) * 16;

    // load 32ch x 256px slab: 8 x LDG.128 per thread
    #pragma unroll
    for (int i = 0; i < 8; ++i) {
        int f4 = i * 256 + tid;          // 0..2047
        int ch = f4 >> 6;                // 0..31
        int p4 = f4 & 63;
        int sr = p4 >> 2;                // window row 0..15
        int w4 = (p4 & 3) << 2;          // col offset 0,4,8,12
        const float4 v = *reinterpret_cast<const float4*>(
            &src[(size_t)ch * HW + (size_t)(h0 + sr) * WID + w0 + w4]);
        int s = sr * 16 + w4;            // token = 4*p4
        ts[ch][s    ] = v.x;
        ts[ch][s + 1] = v.y;
        ts[ch][s + 2] = v.z;
        ts[ch][s + 3] = v.w;
    }
    __syncthreads();

    // write 256 tokens x 32 halves: 4 x STG.128 per thread (8 halves each)
    #pragma unroll
    for (int j = 0; j < 4; ++j) {
        int linear = j * 256 + tid;      // 0..1023
        int s = linear >> 2;
        int q = (linear & 3) << 3;       // half offset 0,8,16,24
        uint4 u;
        u.x = h2u(__floats2half2_rn(ts[q    ][s], ts[q + 1][s]));
        u.y = h2u(__floats2half2_rn(ts[q + 2][s], ts[q + 3][s]));
        u.z = h2u(__floats2half2_rn(ts[q + 4][s], ts[q + 5][s]));
        u.w = h2u(__floats2half2_rn(ts[q + 6][s], ts[q + 7][s]));
        *reinterpret_cast<uint4*>(dst + (size_t)s * C_DIM + q) = u;
    }
}

// ---------------- projection GEMM (fp16 mma, direct-B all modes) -------------
// out[m,n] = sum_k W[m,k] * X[k,n] + bias[m]
// MODE 0: -> g_qh (scaled); MODE 1: M=512 fused K+V; MODE 3: -> output image
#define G_LD   40
#define G_AB_H (128 * G_LD)                    // 5120 halves per tile
#define GEMM_SMEM (3 * G_AB_H * 2 * 2)         // 61,440 B

template<int MODE>
__global__ __launch_bounds__(128, 2)
void gemm_f16_kernel(const __half* __restrict__ Wh,
                     const __half* __restrict__ Xh,
                     const float* __restrict__ bias,
                     float* __restrict__ out_img)
{
    extern __shared__ char smraw[];
    __half* Ah = (__half*)smraw;               // [3][5120]
    __half* Bh = Ah + 3 * G_AB_H;              // [3][5120]

    const int n0  = blockIdx.x * 128;
    const int m0  = blockIdx.y * 128;
    const int b   = blockIdx.z;
    const int tid  = threadIdx.x;
    const int lane = tid & 31;
    const int warp = tid >> 5;
    const int wm   = warp & 1;
    const int wn   = warp >> 1;
    const int g    = lane >> 2;
    const int tig  = lane & 3;

    const __half* Xbh = Xh + ((size_t)(b * WINS_B + (n0 >> 8)) * S_TOK
                              + (n0 & 255)) * (size_t)C_DIM;

    float acc[4][8][4];
    #pragma unroll
    for (int i = 0; i < 4; ++i)
        #pragma unroll
        for (int j = 0; j < 8; ++j)
            #pragma unroll
            for (int r = 0; r < 4; ++r) acc[i][j][r] = 0.f;

    auto load_stage = [&](int kb, int st) {
        const int k0 = kb * 32;
        __half* As = Ah + st * G_AB_H;
        __half* Bs = Bh + st * G_AB_H;
        #pragma unroll
        for (int i = 0; i < 4; ++i) {
            int idx = i * 128 + tid;
            int row = idx >> 2, c8 = (idx & 3) << 3;
            cp_async16(As + row * G_LD + c8,
                       Wh + (size_t)(m0 + row) * C_DIM + k0 + c8);
            cp_async16(Bs + row * G_LD + c8,
                       Xbh + (size_t)row * C_DIM + k0 + c8);
        }
        cp_commit();
    };

    load_stage(0, 0);
    load_stage(1, 1);

    for (int kb = 0; kb < 8; ++kb) {
        const int st = kb % 3;
        if (kb < 7) cp_wait<1>(); else cp_wait<0>();
        __syncthreads();
        if (kb + 2 < 8) load_stage(kb + 2, (kb + 2) % 3);

        const __half* Ab = Ah + st * G_AB_H;
        const __half* Bb = Bh + st * G_AB_H;
        #pragma unroll
        for (int ks = 0; ks < 2; ++ks) {
            uint32_t af[4][4];
            #pragma unroll
            for (int fm = 0; fm < 4; ++fm) {
                int rb = wm * 64 + fm * 16;
                const __half* base = Ab + ks * 16 + 2 * tig;
                af[fm][0] = ldu32(base + (rb + g    ) * G_LD);
                af[fm][1] = ldu32(base + (rb + g + 8) * G_LD);
                af[fm][2] = ldu32(base + (rb + g    ) * G_LD + 8);
                af[fm][3] = ldu32(base + (rb + g + 8) * G_LD + 8);
            }
            uint32_t bf[8][2];
            #pragma unroll
            for (int fn = 0; fn < 8; ++fn) {
                int nb = wn * 64 + fn * 8;
                const __half* base = Bb + ks * 16 + 2 * tig;
                bf[fn][0] = ldu32(base + (nb + g) * G_LD);
                bf[fn][1] = ldu32(base + (nb + g) * G_LD + 8);
            }
            #pragma unroll
            for (int fm = 0; fm < 4; ++fm)
                #pragma unroll
                for (int fn = 0; fn < 8; ++fn)
                    mma_f16(acc[fm][fn], af[fm], bf[fn]);
        }
    }

    // -------- epilogue (n is window-token order for all modes) --------
    if (MODE < 3) {
        const float sc = (MODE == 0) ? SCALE_F : 1.0f;
        #pragma unroll
        for (int fm = 0; fm < 4; ++fm) {
            int row0 = m0 + wm * 64 + fm * 16 + g;
            int row1 = row0 + 8;
            float b0v = bias[row0], b1v = bias[row1];
            #pragma unroll
            for (int fn = 0; fn < 8; ++fn) {
                int ncol = n0 + wn * 64 + fn * 8 + tig * 2;
                #pragma unroll
                for (int e = 0; e < 2; ++e) {
                    int n   = ncol + e;
                    int win = b * WINS_B + (n >> 8);
                    int s   = n & 255;
                    __half v0 = __float2half_rn((acc[fm][fn][e]     + b0v) * sc);
                    __half v1 = __float2half_rn((acc[fm][fn][2 + e] + b1v) * sc);
                    #pragma unroll
                    for (int rr = 0; rr < 2; ++rr) {
                        int row = rr ? row1 : row0;
                        __half v = rr ? v1 : v0;
                        if (MODE == 1 && row >= 256) {       // V rows
                            int r = row - 256;
                            g_vh[((size_t)(win * HEADS + (r >> 5)) * HD + (r & 31))
                                 * S_TOK + s] = v;
                        } else {                              // Q or K rows
                            __half* dst = (MODE == 0) ? g_qh : g_kh;
                            dst[((size_t)(win * HEADS + ((row & 255) >> 5)) * S_TOK + s)
                                * HD + (row & 31)] = v;
                        }
                    }
                }
            }
        }
    } else {
        #pragma unroll
        for (int fm = 0; fm < 4; ++fm) {
            int row0 = m0 + wm * 64 + fm * 16 + g;
            int row1 = row0 + 8;
            float b0v = bias[row0], b1v = bias[row1];
            float* o0 = out_img + (size_t)b * CHW + (size_t)row0 * HW;
            float* o1 = out_img + (size_t)b * CHW + (size_t)row1 * HW;
            #pragma unroll
            for (int fn = 0; fn < 8; ++fn) {
                int ncol = n0 + wn * 64 + fn * 8 + tig * 2;
                #pragma unroll
                for (int e = 0; e < 2; ++e) {
                    int n  = ncol + e;
                    int wl = n >> 8;
                    int s  = n & 255;
                    int h  = ((wl / NWIN) << 4) | (s >> 4);
                    int w  = ((wl % NWIN) << 4) | (s & 15);
                    int pix = h * WID + w;
                    o0[pix] = acc[fm][fn][e]     + b0v;
                    o1[pix] = acc[fm][fn][2 + e] + b1v;
                }
            }
        }
    }
}

// ---------------- attention core (fp16 mma, flash-style; unchanged) ----------
#define AT_LD   40
#define AT_VLD  264
#define ATT_SMEM ((S_TOK*AT_LD + HD*AT_VLD + S_TOK*AT_LD) * 2)   // 57,856 B

__global__ __launch_bounds__(256, 2)
void attn_f16_kernel()
{
    extern __shared__ char smraw[];
    __half* Ksh = (__half*)smraw;                 // [256][40]
    __half* Vsh = Ksh + S_TOK * AT_LD;            // [32][264]
    __half* QP  = Vsh + HD * AT_VLD;              // Q staging, then P

    const int wh   = blockIdx.x;
    const int tid  = threadIdx.x;
    const int lane = tid & 31;
    const int warp = tid >> 5;
    const int g    = lane >> 2;
    const int tig  = lane & 3;

    const __half* qb = g_qh + (size_t)wh * (S_TOK * HD);
    const __half* kb = g_kh + (size_t)wh * (S_TOK * HD);
    const __half* vb = g_vh + (size_t)wh * (HD * S_TOK);

    #pragma unroll
    for (int i = 0; i < 4; ++i) {
        int idx = i * 256 + tid;
        int r   = idx >> 2, c8 = (idx & 3) << 3;
        cp_async16(Ksh + r * AT_LD + c8, kb + r * HD + c8);
        cp_async16(QP  + r * AT_LD + c8, qb + r * HD + c8);
        int d = idx >> 5, cv = (idx & 31) << 3;
        cp_async16(Vsh + d * AT_VLD + cv, vb + d * S_TOK + cv);
    }
    cp_commit();
    cp_wait<0>();
    __syncthreads();

    const int mb = warp * 32;
    uint32_t Qf[2][2][4];
    #pragma unroll
    for (int mt = 0; mt < 2; ++mt)
        #pragma unroll
        for (int ks = 0; ks < 2; ++ks) {
            int rb = mb + mt * 16;
            const __half* base = QP + ks * 16 + 2 * tig;
            Qf[mt][ks][0] = ldu32(base + (rb + g    ) * AT_LD);
            Qf[mt][ks][1] = ldu32(base + (rb + g + 8) * AT_LD);
            Qf[mt][ks][2] = ldu32(base + (rb + g    ) * AT_LD + 8);
            Qf[mt][ks][3] = ldu32(base + (rb + g + 8) * AT_LD + 8);
        }
    __syncthreads();

    __half* Pw = QP + warp * (32 * AT_LD);

    float Oa[2][4][4];
    #pragma unroll
    for (int mt = 0; mt < 2; ++mt)
        #pragma unroll
        for (int nd = 0; nd < 4; ++nd)
            #pragma unroll
            for (int r = 0; r < 4; ++r) Oa[mt][nd][r] = 0.f;
    float rs[4] = {0.f, 0.f, 0.f, 0.f};

    for (int kt = 0; kt < 8; ++kt) {
        const int t0 = kt * 32;
        float Sa[2][4][4];
        #pragma unroll
        for (int mt = 0; mt < 2; ++mt)
            #pragma unroll
            for (int n = 0; n < 4; ++n)
                #pragma unroll
                for (int r = 0; r < 4; ++r) Sa[mt][n][r] = 0.f;

        #pragma unroll
        for (int ks = 0; ks < 2; ++ks)
            #pragma unroll
            for (int nt = 0; nt < 4; ++nt) {
                const __half* base = Ksh + (t0 + nt * 8 + g) * AT_LD
                                         + ks * 16 + 2 * tig;
                uint32_t bfr[2];
                bfr[0] = ldu32(base);
                bfr[1] = ldu32(base + 8);
                mma_f16(Sa[0][nt], Qf[0][ks], bfr);
                mma_f16(Sa[1][nt], Qf[1][ks], bfr);
            }

        #pragma unroll
        for (int mt = 0; mt < 2; ++mt)
            #pragma unroll
            for (int nt = 0; nt < 4; ++nt) {
                float p0 = __expf(Sa[mt][nt][0]);
                float p1 = __expf(Sa[mt][nt][1]);
                float p2 = __expf(Sa[mt][nt][2]);
                float p3 = __expf(Sa[mt][nt][3]);
                rs[mt*2 + 0] += p0 + p1;
                rs[mt*2 + 1] += p2 + p3;
                *reinterpret_cast<__half2*>(
                    Pw + (mt*16 + g    ) * AT_LD + nt*8 + 2*tig)
                    = __floats2half2_rn(p0, p1);
                *reinterpret_cast<__half2*>(
                    Pw + (mt*16 + g + 8) * AT_LD + nt*8 + 2*tig)
                    = __floats2half2_rn(p2, p3);
            }
        __syncwarp();

        #pragma unroll
        for (int ks = 0; ks < 2; ++ks) {
            uint32_t a[2][4];
            #pragma unroll
            for (int mt = 0; mt < 2; ++mt) {
                const __half* base = Pw + ks * 16 + 2 * tig;
                a[mt][0] = ldu32(base + (mt*16 + g    ) * AT_LD);
                a[mt][1] = ldu32(base + (mt*16 + g + 8) * AT_LD);
                a[mt][2] = ldu32(base + (mt*16 + g    ) * AT_LD + 8);
                a[mt][3] = ldu32(base + (mt*16 + g + 8) * AT_LD + 8);
            }
            #pragma unroll
            for (int nd = 0; nd < 4; ++nd) {
                const __half* base = Vsh + (nd*8 + g) * AT_VLD
                                         + t0 + ks * 16 + 2 * tig;
                uint32_t bfr[2];
                bfr[0] = ldu32(base);
                bfr[1] = ldu32(base + 8);
                mma_f16(Oa[0][nd], a[0], bfr);
                mma_f16(Oa[1][nd], a[1], bfr);
            }
        }
        __syncwarp();
    }

    #pragma unroll
    for (int r = 0; r < 4; ++r) {
        rs[r] += __shfl_xor_sync(0xffffffffu, rs[r], 1);
        rs[r] += __shfl_xor_sync(0xffffffffu, rs[r], 2);
    }
    float inv[4];
    #pragma unroll
    for (int r = 0; r < 4; ++r) inv[r] = 1.0f / rs[r];

    const int win  = wh >> 3;
    const int head = wh & 7;
    __half* ob = g_attnh + (size_t)win * (S_TOK * C_DIM) + head * HD;
    #pragma unroll
    for (int mt = 0; mt < 2; ++mt)
        #pragma unroll
        for (int nd = 0; nd < 4; ++nd) {
            int s0 = mb + mt * 16 + g;
            int d0 = nd * 8 + 2 * tig;
            *reinterpret_cast<__half2*>(ob + (size_t)s0 * C_DIM + d0)
                = __floats2half2_rn(Oa[mt][nd][0] * inv[mt*2],
                                    Oa[mt][nd][1] * inv[mt*2]);
            *reinterpret_cast<__half2*>(ob + (size_t)(s0 + 8) * C_DIM + d0)
                = __floats2half2_rn(Oa[mt][nd][2] * inv[mt*2 + 1],
                                    Oa[mt][nd][3] * inv[mt*2 + 1]);
        }
}

// ---------------- launch ---------------------------------------------------
extern "C" void kernel_launch(void* const* d_in, const int* in_sizes, int n_in,
                              void* d_out, int out_size)
{
    const float* x_q  = (const float*)d_in[0];
    const float* x_kv = (const float*)d_in[1];
    const float* Wq   = (const float*)d_in[2];
    const float* bq   = (const float*)d_in[3];
    const float* Wk   = (const float*)d_in[4];
    const float* bk   = (const float*)d_in[5];
    const float* Wv   = (const float*)d_in[6];
    const float* bv   = (const float*)d_in[7];
    const float* Wo   = (const float*)d_in[8];
    const float* bo   = (const float*)d_in[9];
    float* out = (float*)d_out;

    cudaFuncSetAttribute(gemm_f16_kernel<0>,
                         cudaFuncAttributeMaxDynamicSharedMemorySize, GEMM_SMEM);
    cudaFuncSetAttribute(gemm_f16_kernel<1>,
                         cudaFuncAttributeMaxDynamicSharedMemorySize, GEMM_SMEM);
    cudaFuncSetAttribute(gemm_f16_kernel<3>,
                         cudaFuncAttributeMaxDynamicSharedMemorySize, GEMM_SMEM);
    cudaFuncSetAttribute(attn_f16_kernel,
                         cudaFuncAttributeMaxDynamicSharedMemorySize, ATT_SMEM);

    __half *wh_base, *xt_base, *attn_base;
    float  *bkv_base;
    cudaGetSymbolAddress((void**)&wh_base,   g_wh);
    cudaGetSymbolAddress((void**)&xt_base,   g_xth);
    cudaGetSymbolAddress((void**)&attn_base, g_attnh);
    cudaGetSymbolAddress((void**)&bkv_base,  g_bkv);
    const size_t img_str = (size_t)BATCH * WINS_B * S_TOK * C_DIM;

    conv_w_kernel<<<256, 256>>>(Wq, Wk, Wv, Wo, bk, bv);
    conv_x_kernel<<<dim3(WINS_B, BATCH, 16), 256>>>(x_q, x_kv);

    dim3 gq(HW / 128, 2, BATCH);      // (288, 2, 2)
    dim3 gkv(HW / 128, 4, BATCH);     // (288, 4, 2) — K rows 0..255, V rows 256..511
    gemm_f16_kernel<0><<<gq,  128, GEMM_SMEM>>>(wh_base,               xt_base,           bq,       nullptr);
    gemm_f16_kernel<1><<<gkv, 128, GEMM_SMEM>>>(wh_base + C_DIM*C_DIM, xt_base + img_str, bkv_base, nullptr);
    attn_f16_kernel<<<NWH, 256, ATT_SMEM>>>();
    gemm_f16_kernel<3><<<gq,  128, GEMM_SMEM>>>(wh_base + 3*C_DIM*C_DIM, attn_base,       bo,       out);
}

// round 13
// speedup vs baseline: 1.1310x; 1.1310x over previous
#include <cuda_runtime.h>
#include <cuda_fp16.h>
#include <cstdint>

#define C_DIM   256
#define HGT     192
#define WID     192
#define HW      (HGT*WID)
#define CHW     (C_DIM*HW)
#define BATCH   2
#define NWIN    12
#define WINS_B  (NWIN*NWIN)
#define NWINS   (BATCH*WINS_B)      // 288
#define HEADS   8
#define HD      32
#define S_TOK   256
#define NWH     (NWINS*HEADS)       // 2304
#define SCALE_F 0.17677669529663688f

// ---------------- scratch (fp16 intermediates) -------------------------------
__device__ __half g_qh[(size_t)NWH * S_TOK * HD];         // [wh][s][d]
__device__ __half g_kh[(size_t)NWH * S_TOK * HD];         // [wh][t][d]
__device__ __half g_vh[(size_t)NWH * HD * S_TOK];         // [wh][d][t]
__device__ __half g_attnh[(size_t)NWINS * S_TOK * C_DIM]; // [win][s][c]
__device__ __half g_wh[4 * C_DIM * C_DIM];                // Wq,Wk,Wv,Wo fp16

// ---------------- helpers ----------------------------------------------------
__device__ __forceinline__ void mma_f16(float c[4],
                                        const uint32_t a[4],
                                        const uint32_t b[2]) {
    asm volatile(
        "mma.sync.aligned.m16n8k16.row.col.f32.f16.f16.f32 "
        "{%0,%1,%2,%3},{%4,%5,%6,%7},{%8,%9},{%0,%1,%2,%3};"
        : "+f"(c[0]), "+f"(c[1]), "+f"(c[2]), "+f"(c[3])
        : "r"(a[0]), "r"(a[1]), "r"(a[2]), "r"(a[3]),
          "r"(b[0]), "r"(b[1]));
}

__device__ __forceinline__ void cp_async16(void* smem, const void* gmem) {
    unsigned sa = (unsigned)__cvta_generic_to_shared(smem);
    asm volatile("cp.async.cg.shared.global [%0], [%1], 16;" :: "r"(sa), "l"(gmem));
}
__device__ __forceinline__ void cp_commit() {
    asm volatile("cp.async.commit_group;");
}
template<int N> __device__ __forceinline__ void cp_wait() {
    asm volatile("cp.async.wait_group %0;" :: "n"(N));
}
__device__ __forceinline__ uint32_t ldu32(const __half* p) {
    return *reinterpret_cast<const uint32_t*>(p);
}
__device__ __forceinline__ void ldsm_x2_trans(uint32_t& r0, uint32_t& r1,
                                              uint32_t addr) {
    asm volatile("ldmatrix.sync.aligned.m8n8.x2.trans.shared.b16 {%0,%1}, [%2];"
                 : "=r"(r0), "=r"(r1) : "r"(addr));
}

// ---------------- weight conversion ------------------------------------------
__global__ void conv_w_kernel(const float* __restrict__ Wq,
                              const float* __restrict__ Wk,
                              const float* __restrict__ Wv,
                              const float* __restrict__ Wo)
{
    int i = blockIdx.x * blockDim.x + threadIdx.x;
    if (i < C_DIM * C_DIM) {
        g_wh[                 i] = __float2half_rn(Wq[i]);
        g_wh[  C_DIM*C_DIM + i] = __float2half_rn(Wk[i]);
        g_wh[2*C_DIM*C_DIM + i] = __float2half_rn(Wv[i]);
        g_wh[3*C_DIM*C_DIM + i] = __float2half_rn(Wo[i]);
    }
}

// ---------------- projection GEMM (fp16 mma) ---------------------------------
// out[m,n] = sum_k W[m,k] * X[k,n] + bias[m]
// MODE 0/1/2: X fp32 image (raster n). B staged fp32 [k][n], elementwise
//   convert to fp16 [k][136], B-frags via ldmatrix.trans. Out -> g_qh/g_kh/g_vh.
// MODE 3: B fp16 direct from g_attnh [win][s][c] (window-token n). Out -> image.
#define G_LD   40
#define G_AB_H (128 * G_LD)                    // 5120 halves per A tile
#define G_BLD  136                             // B cvt row: halves (pad 8)
#define G_BS_H (32 * G_BLD)                    // 4352 halves per B cvt tile
#define G_XS_F (32 * 128)                      // 4096 floats staging
#define GEMM_SMEM_CVT (3*G_AB_H*2 + 3*G_XS_F*4 + 2*G_BS_H*2)  // 97,280 B
#define GEMM_SMEM_DIR (3*G_AB_H*2 * 2)                        // 61,440 B

template<int MODE>
__global__ __launch_bounds__(128, 2)
void gemm_f16_kernel(const __half* __restrict__ Wh,
                     const float* __restrict__ Xf,
                     const __half* __restrict__ Xh,
                     const float* __restrict__ bias,
                     float* __restrict__ out_img)
{
    constexpr bool CVT = (MODE < 3);
    extern __shared__ char smraw[];
    __half* Ah  = (__half*)smraw;                             // [3][5120]
    float*  Xst = (float*)(smraw + 3 * G_AB_H * 2);           // [3][4096] (CVT)
    __half* Bs  = (__half*)(smraw + 3*G_AB_H*2 + 3*G_XS_F*4); // [2][4352] (CVT)
    __half* Bh  = (__half*)(smraw + 3 * G_AB_H * 2);          // [3][5120] (DIR)

    const int n0  = blockIdx.x * 128;
    const int m0  = blockIdx.y * 128;
    const int b   = blockIdx.z;
    const int tid  = threadIdx.x;
    const int lane = tid & 31;
    const int warp = tid >> 5;
    const int wm   = warp & 1;
    const int wn   = warp >> 1;
    const int g    = lane >> 2;
    const int tig  = lane & 3;

    const float* Xb = nullptr;
    const __half* Xbh = nullptr;
    if (CVT) {
        Xb = Xf + (size_t)b * CHW + n0;
    } else {
        Xbh = Xh + ((size_t)(b * WINS_B + (n0 >> 8)) * S_TOK
                    + (n0 & 255)) * (size_t)C_DIM;
    }

    float acc[4][8][4];
    #pragma unroll
    for (int i = 0; i < 4; ++i)
        #pragma unroll
        for (int j = 0; j < 8; ++j)
            #pragma unroll
            for (int r = 0; r < 4; ++r) acc[i][j][r] = 0.f;

    auto load_stage = [&](int kb, int st) {
        const int k0 = kb * 32;
        __half* As = Ah + st * G_AB_H;
        #pragma unroll
        for (int i = 0; i < 4; ++i) {              // A: 128x32 fp16
            int idx = i * 128 + tid;
            int row = idx >> 2, c8 = (idx & 3) << 3;
            cp_async16(As + row * G_LD + c8,
                       Wh + (size_t)(m0 + row) * C_DIM + k0 + c8);
        }
        if (CVT) {
            float* Xs = Xst + st * G_XS_F;
            #pragma unroll
            for (int i = 0; i < 8; ++i) {          // X: 32x128 fp32 [k][n]
                int idx = i * 128 + tid;
                int k = idx >> 5, c4 = (idx & 31) << 2;
                cp_async16(Xs + k * 128 + c4,
                           Xb + (size_t)(k0 + k) * HW + c4);
            }
        } else {
            __half* Bsd = Bh + st * G_AB_H;
            #pragma unroll
            for (int i = 0; i < 4; ++i) {          // B: 128x32 fp16 [n][k]
                int idx = i * 128 + tid;
                int row = idx >> 2, c8 = (idx & 3) << 3;
                cp_async16(Bsd + row * G_LD + c8,
                           Xbh + (size_t)row * C_DIM + k0 + c8);
            }
        }
        cp_commit();
    };

    load_stage(0, 0);
    load_stage(1, 1);

    const uint32_t bsAddr = (uint32_t)__cvta_generic_to_shared(Bs);
    const int lrow = lane & 15;

    for (int kb = 0; kb < 8; ++kb) {
        const int st = kb % 3;
        if (kb < 7) cp_wait<1>(); else cp_wait<0>();
        __syncthreads();

        if (CVT) {
            // elementwise fp32 -> fp16, [k][128] -> [k][136] (conflict-free)
            const float* Xs = Xst + st * G_XS_F;
            __half* Bc = Bs + (kb & 1) * G_BS_H;
            #pragma unroll
            for (int j = 0; j < 16; ++j) {
                int idx = j * 128 + tid;           // 0..2047 half2 slots
                int k = idx >> 6, p = (idx & 63) << 1;
                float2 f = *reinterpret_cast<const float2*>(Xs + k * 128 + p);
                *reinterpret_cast<__half2*>(Bc + k * G_BLD + p)
                    = __floats2half2_rn(f.x, f.y);
            }
            __syncthreads();
        }
        if (kb + 2 < 8) load_stage(kb + 2, (kb + 2) % 3);

        const __half* Ab = Ah + st * G_AB_H;
        const uint32_t bRow0 = bsAddr + ((kb & 1) * G_BS_H + lrow * G_BLD) * 2
                             + wn * 64 * 2;       // CVT path base (bytes)
        const __half* Bb = Bh + st * G_AB_H;      // DIR path

        #pragma unroll
        for (int ks = 0; ks < 2; ++ks) {
            uint32_t af[4][4];
            #pragma unroll
            for (int fm = 0; fm < 4; ++fm) {
                int rb = wm * 64 + fm * 16;
                const __half* base = Ab + ks * 16 + 2 * tig;
                af[fm][0] = ldu32(base + (rb + g    ) * G_LD);
                af[fm][1] = ldu32(base + (rb + g + 8) * G_LD);
                af[fm][2] = ldu32(base + (rb + g    ) * G_LD + 8);
                af[fm][3] = ldu32(base + (rb + g + 8) * G_LD + 8);
            }
            uint32_t bf[8][2];
            if (CVT) {
                const uint32_t rowA = bRow0 + (ks * 16) * G_BLD * 2;
                #pragma unroll
                for (int fn = 0; fn < 8; ++fn)
                    ldsm_x2_trans(bf[fn][0], bf[fn][1], rowA + fn * 16);
            } else {
                #pragma unroll
                for (int fn = 0; fn < 8; ++fn) {
                    int nb = wn * 64 + fn * 8;
                    const __half* base = Bb + ks * 16 + 2 * tig;
                    bf[fn][0] = ldu32(base + (nb + g) * G_LD);
                    bf[fn][1] = ldu32(base + (nb + g) * G_LD + 8);
                }
            }
            #pragma unroll
            for (int fm = 0; fm < 4; ++fm)
                #pragma unroll
                for (int fn = 0; fn < 8; ++fn)
                    mma_f16(acc[fm][fn], af[fm], bf[fn]);
        }
    }

    // -------- epilogue --------
    if (MODE < 3) {
        // n is raster pixel order -> windowize per element
        const float sc = (MODE == 0) ? SCALE_F : 1.0f;
        #pragma unroll
        for (int fm = 0; fm < 4; ++fm) {
            int row0 = m0 + wm * 64 + fm * 16 + g;
            int row1 = row0 + 8;
            float b0v = bias[row0], b1v = bias[row1];
            int head0 = row0 >> 5, hd0 = row0 & 31;
            int head1 = row1 >> 5, hd1 = row1 & 31;
            #pragma unroll
            for (int fn = 0; fn < 8; ++fn) {
                int ncol = n0 + wn * 64 + fn * 8 + tig * 2;
                #pragma unroll
                for (int e = 0; e < 2; ++e) {
                    int n   = ncol + e;
                    int h   = n / WID;
                    int w   = n - h * WID;
                    int win = b * WINS_B + (h >> 4) * NWIN + (w >> 4);
                    int s   = ((h & 15) << 4) | (w & 15);
                    __half v0 = __float2half_rn((acc[fm][fn][e]     + b0v) * sc);
                    __half v1 = __float2half_rn((acc[fm][fn][2 + e] + b1v) * sc);
                    if (MODE == 2) {
                        g_vh[((size_t)(win * HEADS + head0) * HD + hd0) * S_TOK + s] = v0;
                        g_vh[((size_t)(win * HEADS + head1) * HD + hd1) * S_TOK + s] = v1;
                    } else {
                        __half* dst = (MODE == 0) ? g_qh : g_kh;
                        dst[((size_t)(win * HEADS + head0) * S_TOK + s) * HD + hd0] = v0;
                        dst[((size_t)(win * HEADS + head1) * S_TOK + s) * HD + hd1] = v1;
                    }
                }
            }
        }
    } else {
        #pragma unroll
        for (int fm = 0; fm < 4; ++fm) {
            int row0 = m0 + wm * 64 + fm * 16 + g;
            int row1 = row0 + 8;
            float b0v = bias[row0], b1v = bias[row1];
            float* o0 = out_img + (size_t)b * CHW + (size_t)row0 * HW;
            float* o1 = out_img + (size_t)b * CHW + (size_t)row1 * HW;
            #pragma unroll
            for (int fn = 0; fn < 8; ++fn) {
                int ncol = n0 + wn * 64 + fn * 8 + tig * 2;
                #pragma unroll
                for (int e = 0; e < 2; ++e) {
                    int n  = ncol + e;
                    int wl = n >> 8;
                    int s  = n & 255;
                    int h  = ((wl / NWIN) << 4) | (s >> 4);
                    int w  = ((wl % NWIN) << 4) | (s & 15);
                    int pix = h * WID + w;
                    o0[pix] = acc[fm][fn][e]     + b0v;
                    o1[pix] = acc[fm][fn][2 + e] + b1v;
                }
            }
        }
    }
}

// ---------------- attention core (fp16 mma, flash-style; unchanged) ----------
#define AT_LD   40
#define AT_VLD  264
#define ATT_SMEM ((S_TOK*AT_LD + HD*AT_VLD + S_TOK*AT_LD) * 2)   // 57,856 B

__global__ __launch_bounds__(256, 2)
void attn_f16_kernel()
{
    extern __shared__ char smraw[];
    __half* Ksh = (__half*)smraw;                 // [256][40]
    __half* Vsh = Ksh + S_TOK * AT_LD;            // [32][264]
    __half* QP  = Vsh + HD * AT_VLD;              // Q staging, then P

    const int wh   = blockIdx.x;
    const int tid  = threadIdx.x;
    const int lane = tid & 31;
    const int warp = tid >> 5;
    const int g    = lane >> 2;
    const int tig  = lane & 3;

    const __half* qb = g_qh + (size_t)wh * (S_TOK * HD);
    const __half* kb = g_kh + (size_t)wh * (S_TOK * HD);
    const __half* vb = g_vh + (size_t)wh * (HD * S_TOK);

    #pragma unroll
    for (int i = 0; i < 4; ++i) {
        int idx = i * 256 + tid;
        int r   = idx >> 2, c8 = (idx & 3) << 3;
        cp_async16(Ksh + r * AT_LD + c8, kb + r * HD + c8);
        cp_async16(QP  + r * AT_LD + c8, qb + r * HD + c8);
        int d = idx >> 5, cv = (idx & 31) << 3;
        cp_async16(Vsh + d * AT_VLD + cv, vb + d * S_TOK + cv);
    }
    cp_commit();
    cp_wait<0>();
    __syncthreads();

    const int mb = warp * 32;
    uint32_t Qf[2][2][4];
    #pragma unroll
    for (int mt = 0; mt < 2; ++mt)
        #pragma unroll
        for (int ks = 0; ks < 2; ++ks) {
            int rb = mb + mt * 16;
            const __half* base = QP + ks * 16 + 2 * tig;
            Qf[mt][ks][0] = ldu32(base + (rb + g    ) * AT_LD);
            Qf[mt][ks][1] = ldu32(base + (rb + g + 8) * AT_LD);
            Qf[mt][ks][2] = ldu32(base + (rb + g    ) * AT_LD + 8);
            Qf[mt][ks][3] = ldu32(base + (rb + g + 8) * AT_LD + 8);
        }
    __syncthreads();

    __half* Pw = QP + warp * (32 * AT_LD);

    float Oa[2][4][4];
    #pragma unroll
    for (int mt = 0; mt < 2; ++mt)
        #pragma unroll
        for (int nd = 0; nd < 4; ++nd)
            #pragma unroll
            for (int r = 0; r < 4; ++r) Oa[mt][nd][r] = 0.f;
    float rs[4] = {0.f, 0.f, 0.f, 0.f};

    for (int kt = 0; kt < 8; ++kt) {
        const int t0 = kt * 32;
        float Sa[2][4][4];
        #pragma unroll
        for (int mt = 0; mt < 2; ++mt)
            #pragma unroll
            for (int n = 0; n < 4; ++n)
                #pragma unroll
                for (int r = 0; r < 4; ++r) Sa[mt][n][r] = 0.f;

        #pragma unroll
        for (int ks = 0; ks < 2; ++ks)
            #pragma unroll
            for (int nt = 0; nt < 4; ++nt) {
                const __half* base = Ksh + (t0 + nt * 8 + g) * AT_LD
                                         + ks * 16 + 2 * tig;
                uint32_t bfr[2];
                bfr[0] = ldu32(base);
                bfr[1] = ldu32(base + 8);
                mma_f16(Sa[0][nt], Qf[0][ks], bfr);
                mma_f16(Sa[1][nt], Qf[1][ks], bfr);
            }

        #pragma unroll
        for (int mt = 0; mt < 2; ++mt)
            #pragma unroll
            for (int nt = 0; nt < 4; ++nt) {
                float p0 = __expf(Sa[mt][nt][0]);
                float p1 = __expf(Sa[mt][nt][1]);
                float p2 = __expf(Sa[mt][nt][2]);
                float p3 = __expf(Sa[mt][nt][3]);
                rs[mt*2 + 0] += p0 + p1;
                rs[mt*2 + 1] += p2 + p3;
                *reinterpret_cast<__half2*>(
                    Pw + (mt*16 + g    ) * AT_LD + nt*8 + 2*tig)
                    = __floats2half2_rn(p0, p1);
                *reinterpret_cast<__half2*>(
                    Pw + (mt*16 + g + 8) * AT_LD + nt*8 + 2*tig)
                    = __floats2half2_rn(p2, p3);
            }
        __syncwarp();

        #pragma unroll
        for (int ks = 0; ks < 2; ++ks) {
            uint32_t a[2][4];
            #pragma unroll
            for (int mt = 0; mt < 2; ++mt) {
                const __half* base = Pw + ks * 16 + 2 * tig;
                a[mt][0] = ldu32(base + (mt*16 + g    ) * AT_LD);
                a[mt][1] = ldu32(base + (mt*16 + g + 8) * AT_LD);
                a[mt][2] = ldu32(base + (mt*16 + g    ) * AT_LD + 8);
                a[mt][3] = ldu32(base + (mt*16 + g + 8) * AT_LD + 8);
            }
            #pragma unroll
            for (int nd = 0; nd < 4; ++nd) {
                const __half* base = Vsh + (nd*8 + g) * AT_VLD
                                         + t0 + ks * 16 + 2 * tig;
                uint32_t bfr[2];
                bfr[0] = ldu32(base);
                bfr[1] = ldu32(base + 8);
                mma_f16(Oa[0][nd], a[0], bfr);
                mma_f16(Oa[1][nd], a[1], bfr);
            }
        }
        __syncwarp();
    }

    #pragma unroll
    for (int r = 0; r < 4; ++r) {
        rs[r] += __shfl_xor_sync(0xffffffffu, rs[r], 1);
        rs[r] += __shfl_xor_sync(0xffffffffu, rs[r], 2);
    }
    float inv[4];
    #pragma unroll
    for (int r = 0; r < 4; ++r) inv[r] = 1.0f / rs[r];

    const int win  = wh >> 3;
    const int head = wh & 7;
    __half* ob = g_attnh + (size_t)win * (S_TOK * C_DIM) + head * HD;
    #pragma unroll
    for (int mt = 0; mt < 2; ++mt)
        #pragma unroll
        for (int nd = 0; nd < 4; ++nd) {
            int s0 = mb + mt * 16 + g;
            int d0 = nd * 8 + 2 * tig;
            *reinterpret_cast<__half2*>(ob + (size_t)s0 * C_DIM + d0)
                = __floats2half2_rn(Oa[mt][nd][0] * inv[mt*2],
                                    Oa[mt][nd][1] * inv[mt*2]);
            *reinterpret_cast<__half2*>(ob + (size_t)(s0 + 8) * C_DIM + d0)
                = __floats2half2_rn(Oa[mt][nd][2] * inv[mt*2 + 1],
                                    Oa[mt][nd][3] * inv[mt*2 + 1]);
        }
}

// ---------------- launch ---------------------------------------------------
extern "C" void kernel_launch(void* const* d_in, const int* in_sizes, int n_in,
                              void* d_out, int out_size)
{
    const float* x_q  = (const float*)d_in[0];
    const float* x_kv = (const float*)d_in[1];
    const float* Wq   = (const float*)d_in[2];
    const float* bq   = (const float*)d_in[3];
    const float* Wk   = (const float*)d_in[4];
    const float* bk   = (const float*)d_in[5];
    const float* Wv   = (const float*)d_in[6];
    const float* bv   = (const float*)d_in[7];
    const float* Wo   = (const float*)d_in[8];
    const float* bo   = (const float*)d_in[9];
    float* out = (float*)d_out;

    cudaFuncSetAttribute(gemm_f16_kernel<0>,
                         cudaFuncAttributeMaxDynamicSharedMemorySize, GEMM_SMEM_CVT);
    cudaFuncSetAttribute(gemm_f16_kernel<1>,
                         cudaFuncAttributeMaxDynamicSharedMemorySize, GEMM_SMEM_CVT);
    cudaFuncSetAttribute(gemm_f16_kernel<2>,
                         cudaFuncAttributeMaxDynamicSharedMemorySize, GEMM_SMEM_CVT);
    cudaFuncSetAttribute(gemm_f16_kernel<3>,
                         cudaFuncAttributeMaxDynamicSharedMemorySize, GEMM_SMEM_DIR);
    cudaFuncSetAttribute(attn_f16_kernel,
                         cudaFuncAttributeMaxDynamicSharedMemorySize, ATT_SMEM);

    __half *wh_base, *attn_base;
    cudaGetSymbolAddress((void**)&wh_base,   g_wh);
    cudaGetSymbolAddress((void**)&attn_base, g_attnh);

    conv_w_kernel<<<256, 256>>>(Wq, Wk, Wv, Wo);

    dim3 gq(HW / 128, 2, BATCH);      // (288, 2, 2)
    gemm_f16_kernel<0><<<gq, 128, GEMM_SMEM_CVT>>>(wh_base,                 x_q,  nullptr,   bq, nullptr);
    gemm_f16_kernel<1><<<gq, 128, GEMM_SMEM_CVT>>>(wh_base +   C_DIM*C_DIM, x_kv, nullptr,   bk, nullptr);
    gemm_f16_kernel<2><<<gq, 128, GEMM_SMEM_CVT>>>(wh_base + 2*C_DIM*C_DIM, x_kv, nullptr,   bv, nullptr);
    attn_f16_kernel<<<NWH, 256, ATT_SMEM>>>();
    gemm_f16_kernel<3><<<gq, 128, GEMM_SMEM_DIR>>>(wh_base + 3*C_DIM*C_DIM, nullptr, attn_base, bo, out);
}

// round 14
// speedup vs baseline: 1.1427x; 1.0104x over previous
#include <cuda_runtime.h>
#include <cuda_fp16.h>
#include <cstdint>

#define C_DIM   256
#define HGT     192
#define WID     192
#define HW      (HGT*WID)
#define CHW     (C_DIM*HW)
#define BATCH   2
#define NWIN    12
#define WINS_B  (NWIN*NWIN)
#define NWINS   (BATCH*WINS_B)      // 288
#define HEADS   8
#define HD      32
#define S_TOK   256
#define NWH     (NWINS*HEADS)       // 2304
#define SCALE_F 0.17677669529663688f

// ---------------- scratch (fp16 intermediates) -------------------------------
__device__ __half g_qh[(size_t)NWH * S_TOK * HD];         // [wh][s][d]
__device__ __half g_kh[(size_t)NWH * S_TOK * HD];         // [wh][t][d]
__device__ __half g_vh[(size_t)NWH * HD * S_TOK];         // [wh][d][t]
__device__ __half g_attnh[(size_t)NWINS * S_TOK * C_DIM]; // [win][s][c]
__device__ __half g_wh[4 * C_DIM * C_DIM];                // Wq,Wk,Wv,Wo fp16
__device__ __half g_x16[(size_t)2 * BATCH * CHW];         // x_q ++ x_kv fp16 raster

// ---------------- helpers ----------------------------------------------------
__device__ __forceinline__ void mma_f16(float c[4],
                                        const uint32_t a[4],
                                        const uint32_t b[2]) {
    asm volatile(
        "mma.sync.aligned.m16n8k16.row.col.f32.f16.f16.f32 "
        "{%0,%1,%2,%3},{%4,%5,%6,%7},{%8,%9},{%0,%1,%2,%3};"
        : "+f"(c[0]), "+f"(c[1]), "+f"(c[2]), "+f"(c[3])
        : "r"(a[0]), "r"(a[1]), "r"(a[2]), "r"(a[3]),
          "r"(b[0]), "r"(b[1]));
}

__device__ __forceinline__ void cp_async16(void* smem, const void* gmem) {
    unsigned sa = (unsigned)__cvta_generic_to_shared(smem);
    asm volatile("cp.async.cg.shared.global [%0], [%1], 16;" :: "r"(sa), "l"(gmem));
}
__device__ __forceinline__ void cp_commit() {
    asm volatile("cp.async.commit_group;");
}
template<int N> __device__ __forceinline__ void cp_wait() {
    asm volatile("cp.async.wait_group %0;" :: "n"(N));
}
__device__ __forceinline__ uint32_t ldu32(const __half* p) {
    return *reinterpret_cast<const uint32_t*>(p);
}
__device__ __forceinline__ uint32_t h2u(__half2 h) {
    return *reinterpret_cast<uint32_t*>(&h);
}
__device__ __forceinline__ void ldsm_x2_trans(uint32_t& r0, uint32_t& r1,
                                              uint32_t addr) {
    asm volatile("ldmatrix.sync.aligned.m8n8.x2.trans.shared.b16 {%0,%1}, [%2];"
                 : "=r"(r0), "=r"(r1) : "r"(addr));
}

// ---------------- weight conversion ------------------------------------------
__global__ void conv_w_kernel(const float* __restrict__ Wq,
                              const float* __restrict__ Wk,
                              const float* __restrict__ Wv,
                              const float* __restrict__ Wo)
{
    int i = blockIdx.x * blockDim.x + threadIdx.x;
    if (i < C_DIM * C_DIM) {
        g_wh[                 i] = __float2half_rn(Wq[i]);
        g_wh[  C_DIM*C_DIM + i] = __float2half_rn(Wk[i]);
        g_wh[2*C_DIM*C_DIM + i] = __float2half_rn(Wv[i]);
        g_wh[3*C_DIM*C_DIM + i] = __float2half_rn(Wo[i]);
    }
}

// ---------------- x convert: fp32 raster -> fp16 raster (pure streaming) -----
__global__ __launch_bounds__(256)
void conv_x16_kernel(const float* __restrict__ x_q,
                     const float* __restrict__ x_kv)
{
    const size_t i = (size_t)blockIdx.x * 256 + threadIdx.x;  // 8-elem group
    const size_t N8 = (size_t)BATCH * CHW / 8;                // 2,359,296
    if (i >= N8) return;
    const float* src = blockIdx.y ? x_kv : x_q;
    __half* dst = g_x16 + (size_t)blockIdx.y * BATCH * CHW;
    float4 a = reinterpret_cast<const float4*>(src)[2 * i];
    float4 c = reinterpret_cast<const float4*>(src)[2 * i + 1];
    uint4 u;
    u.x = h2u(__floats2half2_rn(a.x, a.y));
    u.y = h2u(__floats2half2_rn(a.z, a.w));
    u.z = h2u(__floats2half2_rn(c.x, c.y));
    u.w = h2u(__floats2half2_rn(c.z, c.w));
    reinterpret_cast<uint4*>(dst)[i] = u;
}

// ---------------- projection GEMM (fp16 mma) ---------------------------------
// out[m,n] = sum_k W[m,k] * X[k,n] + bias[m]
// MODE 0/1/2: B fp16 raster [k][n] from g_x16, frags via ldmatrix.trans.
// MODE 3: B fp16 [n][k] direct from g_attnh (window-token n). Out -> image.
#define G_LD   40
#define G_AB_H (128 * G_LD)                    // 5120 halves per A tile
#define G_BLD  136                             // B [k][n] row: halves (pad 8)
#define G_BS_H (32 * G_BLD)                    // 4352 halves per B tile
#define GEMM_SMEM_CVT ((3*G_AB_H + 3*G_BS_H) * 2)   // 56,832 B
#define GEMM_SMEM_DIR (3*G_AB_H*2 * 2)              // 61,440 B

template<int MODE>
__global__ __launch_bounds__(128, 2)
void gemm_f16_kernel(const __half* __restrict__ Wh,
                     const __half* __restrict__ Xh,
                     const float* __restrict__ bias,
                     float* __restrict__ out_img)
{
    constexpr bool TRN = (MODE < 3);           // B in [k][n], use ldmatrix.trans
    extern __shared__ char smraw[];
    __half* Ah = (__half*)smraw;                          // [3][5120]
    __half* Bs = (__half*)(smraw + 3 * G_AB_H * 2);       // [3][4352] (TRN)
    __half* Bh = (__half*)(smraw + 3 * G_AB_H * 2);       // [3][5120] (DIR)

    const int n0  = blockIdx.x * 128;
    const int m0  = blockIdx.y * 128;
    const int b   = blockIdx.z;
    const int tid  = threadIdx.x;
    const int lane = tid & 31;
    const int warp = tid >> 5;
    const int wm   = warp & 1;
    const int wn   = warp >> 1;
    const int g    = lane >> 2;
    const int tig  = lane & 3;

    const __half* Xb;
    if (TRN) {
        Xb = Xh + (size_t)b * CHW + n0;                   // [k][n] rows, ld=HW
    } else {
        Xb = Xh + ((size_t)(b * WINS_B + (n0 >> 8)) * S_TOK
                   + (n0 & 255)) * (size_t)C_DIM;         // [n][k] rows, ld=C_DIM
    }

    float acc[4][8][4];
    #pragma unroll
    for (int i = 0; i < 4; ++i)
        #pragma unroll
        for (int j = 0; j < 8; ++j)
            #pragma unroll
            for (int r = 0; r < 4; ++r) acc[i][j][r] = 0.f;

    auto load_stage = [&](int kb, int st) {
        const int k0 = kb * 32;
        __half* As = Ah + st * G_AB_H;
        #pragma unroll
        for (int i = 0; i < 4; ++i) {              // A: 128x32 fp16
            int idx = i * 128 + tid;
            int row = idx >> 2, c8 = (idx & 3) << 3;
            cp_async16(As + row * G_LD + c8,
                       Wh + (size_t)(m0 + row) * C_DIM + k0 + c8);
        }
        if (TRN) {
            __half* Bt = Bs + st * G_BS_H;
            #pragma unroll
            for (int i = 0; i < 4; ++i) {          // B: 32k x 128n fp16
                int idx = i * 128 + tid;
                int k = idx >> 4, c8 = (idx & 15) << 3;
                cp_async16(Bt + k * G_BLD + c8,
                           Xb + (size_t)(k0 + k) * HW + c8);
            }
        } else {
            __half* Bd = Bh + st * G_AB_H;
            #pragma unroll
            for (int i = 0; i < 4; ++i) {          // B: 128n x 32k fp16
                int idx = i * 128 + tid;
                int row = idx >> 2, c8 = (idx & 3) << 3;
                cp_async16(Bd + row * G_LD + c8,
                           Xb + (size_t)row * C_DIM + k0 + c8);
            }
        }
        cp_commit();
    };

    load_stage(0, 0);
    load_stage(1, 1);

    const uint32_t bsAddr = (uint32_t)__cvta_generic_to_shared(Bs);
    const int lrow = lane & 15;

    for (int kb = 0; kb < 8; ++kb) {
        const int st = kb % 3;
        if (kb < 7) cp_wait<1>(); else cp_wait<0>();
        __syncthreads();
        if (kb + 2 < 8) load_stage(kb + 2, (kb + 2) % 3);

        const __half* Ab = Ah + st * G_AB_H;
        const uint32_t bRow0 = bsAddr + (st * G_BS_H + lrow * G_BLD) * 2
                             + wn * 64 * 2;       // TRN base (bytes)
        const __half* Bb = Bh + st * G_AB_H;      // DIR base

        #pragma unroll
        for (int ks = 0; ks < 2; ++ks) {
            uint32_t af[4][4];
            #pragma unroll
            for (int fm = 0; fm < 4; ++fm) {
                int rb = wm * 64 + fm * 16;
                const __half* base = Ab + ks * 16 + 2 * tig;
                af[fm][0] = ldu32(base + (rb + g    ) * G_LD);
                af[fm][1] = ldu32(base + (rb + g + 8) * G_LD);
                af[fm][2] = ldu32(base + (rb + g    ) * G_LD + 8);
                af[fm][3] = ldu32(base + (rb + g + 8) * G_LD + 8);
            }
            uint32_t bf[8][2];
            if (TRN) {
                const uint32_t rowA = bRow0 + (ks * 16) * G_BLD * 2;
                #pragma unroll
                for (int fn = 0; fn < 8; ++fn)
                    ldsm_x2_trans(bf[fn][0], bf[fn][1], rowA + fn * 16);
            } else {
                #pragma unroll
                for (int fn = 0; fn < 8; ++fn) {
                    int nb = wn * 64 + fn * 8;
                    const __half* base = Bb + ks * 16 + 2 * tig;
                    bf[fn][0] = ldu32(base + (nb + g) * G_LD);
                    bf[fn][1] = ldu32(base + (nb + g) * G_LD + 8);
                }
            }
            #pragma unroll
            for (int fm = 0; fm < 4; ++fm)
                #pragma unroll
                for (int fn = 0; fn < 8; ++fn)
                    mma_f16(acc[fm][fn], af[fm], bf[fn]);
        }
    }

    // -------- epilogue --------
    if (MODE < 3) {
        // n is raster pixel order -> windowize per element
        const float sc = (MODE == 0) ? SCALE_F : 1.0f;
        #pragma unroll
        for (int fm = 0; fm < 4; ++fm) {
            int row0 = m0 + wm * 64 + fm * 16 + g;
            int row1 = row0 + 8;
            float b0v = bias[row0], b1v = bias[row1];
            int head0 = row0 >> 5, hd0 = row0 & 31;
            int head1 = row1 >> 5, hd1 = row1 & 31;
            #pragma unroll
            for (int fn = 0; fn < 8; ++fn) {
                int ncol = n0 + wn * 64 + fn * 8 + tig * 2;
                #pragma unroll
                for (int e = 0; e < 2; ++e) {
                    int n   = ncol + e;
                    int h   = n / WID;
                    int w   = n - h * WID;
                    int win = b * WINS_B + (h >> 4) * NWIN + (w >> 4);
                    int s   = ((h & 15) << 4) | (w & 15);
                    __half v0 = __float2half_rn((acc[fm][fn][e]     + b0v) * sc);
                    __half v1 = __float2half_rn((acc[fm][fn][2 + e] + b1v) * sc);
                    if (MODE == 2) {
                        g_vh[((size_t)(win * HEADS + head0) * HD + hd0) * S_TOK + s] = v0;
                        g_vh[((size_t)(win * HEADS + head1) * HD + hd1) * S_TOK + s] = v1;
                    } else {
                        __half* dst = (MODE == 0) ? g_qh : g_kh;
                        dst[((size_t)(win * HEADS + head0) * S_TOK + s) * HD + hd0] = v0;
                        dst[((size_t)(win * HEADS + head1) * S_TOK + s) * HD + hd1] = v1;
                    }
                }
            }
        }
    } else {
        #pragma unroll
        for (int fm = 0; fm < 4; ++fm) {
            int row0 = m0 + wm * 64 + fm * 16 + g;
            int row1 = row0 + 8;
            float b0v = bias[row0], b1v = bias[row1];
            float* o0 = out_img + (size_t)b * CHW + (size_t)row0 * HW;
            float* o1 = out_img + (size_t)b * CHW + (size_t)row1 * HW;
            #pragma unroll
            for (int fn = 0; fn < 8; ++fn) {
                int ncol = n0 + wn * 64 + fn * 8 + tig * 2;
                #pragma unroll
                for (int e = 0; e < 2; ++e) {
                    int n  = ncol + e;
                    int wl = n >> 8;
                    int s  = n & 255;
                    int h  = ((wl / NWIN) << 4) | (s >> 4);
                    int w  = ((wl % NWIN) << 4) | (s & 15);
                    int pix = h * WID + w;
                    o0[pix] = acc[fm][fn][e]     + b0v;
                    o1[pix] = acc[fm][fn][2 + e] + b1v;
                }
            }
        }
    }
}

// ---------------- attention core (fp16 mma, flash-style; unchanged) ----------
#define AT_LD   40
#define AT_VLD  264
#define ATT_SMEM ((S_TOK*AT_LD + HD*AT_VLD + S_TOK*AT_LD) * 2)   // 57,856 B

__global__ __launch_bounds__(256, 2)
void attn_f16_kernel()
{
    extern __shared__ char smraw[];
    __half* Ksh = (__half*)smraw;                 // [256][40]
    __half* Vsh = Ksh + S_TOK * AT_LD;            // [32][264]
    __half* QP  = Vsh + HD * AT_VLD;              // Q staging, then P

    const int wh   = blockIdx.x;
    const int tid  = threadIdx.x;
    const int lane = tid & 31;
    const int warp = tid >> 5;
    const int g    = lane >> 2;
    const int tig  = lane & 3;

    const __half* qb = g_qh + (size_t)wh * (S_TOK * HD);
    const __half* kb = g_kh + (size_t)wh * (S_TOK * HD);
    const __half* vb = g_vh + (size_t)wh * (HD * S_TOK);

    #pragma unroll
    for (int i = 0; i < 4; ++i) {
        int idx = i * 256 + tid;
        int r   = idx >> 2, c8 = (idx & 3) << 3;
        cp_async16(Ksh + r * AT_LD + c8, kb + r * HD + c8);
        cp_async16(QP  + r * AT_LD + c8, qb + r * HD + c8);
        int d = idx >> 5, cv = (idx & 31) << 3;
        cp_async16(Vsh + d * AT_VLD + cv, vb + d * S_TOK + cv);
    }
    cp_commit();
    cp_wait<0>();
    __syncthreads();

    const int mb = warp * 32;
    uint32_t Qf[2][2][4];
    #pragma unroll
    for (int mt = 0; mt < 2; ++mt)
        #pragma unroll
        for (int ks = 0; ks < 2; ++ks) {
            int rb = mb + mt * 16;
            const __half* base = QP + ks * 16 + 2 * tig;
            Qf[mt][ks][0] = ldu32(base + (rb + g    ) * AT_LD);
            Qf[mt][ks][1] = ldu32(base + (rb + g + 8) * AT_LD);
            Qf[mt][ks][2] = ldu32(base + (rb + g    ) * AT_LD + 8);
            Qf[mt][ks][3] = ldu32(base + (rb + g + 8) * AT_LD + 8);
        }
    __syncthreads();

    __half* Pw = QP + warp * (32 * AT_LD);

    float Oa[2][4][4];
    #pragma unroll
    for (int mt = 0; mt < 2; ++mt)
        #pragma unroll
        for (int nd = 0; nd < 4; ++nd)
            #pragma unroll
            for (int r = 0; r < 4; ++r) Oa[mt][nd][r] = 0.f;
    float rs[4] = {0.f, 0.f, 0.f, 0.f};

    for (int kt = 0; kt < 8; ++kt) {
        const int t0 = kt * 32;
        float Sa[2][4][4];
        #pragma unroll
        for (int mt = 0; mt < 2; ++mt)
            #pragma unroll
            for (int n = 0; n < 4; ++n)
                #pragma unroll
                for (int r = 0; r < 4; ++r) Sa[mt][n][r] = 0.f;

        #pragma unroll
        for (int ks = 0; ks < 2; ++ks)
            #pragma unroll
            for (int nt = 0; nt < 4; ++nt) {
                const __half* base = Ksh + (t0 + nt * 8 + g) * AT_LD
                                         + ks * 16 + 2 * tig;
                uint32_t bfr[2];
                bfr[0] = ldu32(base);
                bfr[1] = ldu32(base + 8);
                mma_f16(Sa[0][nt], Qf[0][ks], bfr);
                mma_f16(Sa[1][nt], Qf[1][ks], bfr);
            }

        #pragma unroll
        for (int mt = 0; mt < 2; ++mt)
            #pragma unroll
            for (int nt = 0; nt < 4; ++nt) {
                float p0 = __expf(Sa[mt][nt][0]);
                float p1 = __expf(Sa[mt][nt][1]);
                float p2 = __expf(Sa[mt][nt][2]);
                float p3 = __expf(Sa[mt][nt][3]);
                rs[mt*2 + 0] += p0 + p1;
                rs[mt*2 + 1] += p2 + p3;
                *reinterpret_cast<__half2*>(
                    Pw + (mt*16 + g    ) * AT_LD + nt*8 + 2*tig)
                    = __floats2half2_rn(p0, p1);
                *reinterpret_cast<__half2*>(
                    Pw + (mt*16 + g + 8) * AT_LD + nt*8 + 2*tig)
                    = __floats2half2_rn(p2, p3);
            }
        __syncwarp();

        #pragma unroll
        for (int ks = 0; ks < 2; ++ks) {
            uint32_t a[2][4];
            #pragma unroll
            for (int mt = 0; mt < 2; ++mt) {
                const __half* base = Pw + ks * 16 + 2 * tig;
                a[mt][0] = ldu32(base + (mt*16 + g    ) * AT_LD);
                a[mt][1] = ldu32(base + (mt*16 + g + 8) * AT_LD);
                a[mt][2] = ldu32(base + (mt*16 + g    ) * AT_LD + 8);
                a[mt][3] = ldu32(base + (mt*16 + g + 8) * AT_LD + 8);
            }
            #pragma unroll
            for (int nd = 0; nd < 4; ++nd) {
                const __half* base = Vsh + (nd*8 + g) * AT_VLD
                                         + t0 + ks * 16 + 2 * tig;
                uint32_t bfr[2];
                bfr[0] = ldu32(base);
                bfr[1] = ldu32(base + 8);
                mma_f16(Oa[0][nd], a[0], bfr);
                mma_f16(Oa[1][nd], a[1], bfr);
            }
        }
        __syncwarp();
    }

    #pragma unroll
    for (int r = 0; r < 4; ++r) {
        rs[r] += __shfl_xor_sync(0xffffffffu, rs[r], 1);
        rs[r] += __shfl_xor_sync(0xffffffffu, rs[r], 2);
    }
    float inv[4];
    #pragma unroll
    for (int r = 0; r < 4; ++r) inv[r] = 1.0f / rs[r];

    const int win  = wh >> 3;
    const int head = wh & 7;
    __half* ob = g_attnh + (size_t)win * (S_TOK * C_DIM) + head * HD;
    #pragma unroll
    for (int mt = 0; mt < 2; ++mt)
        #pragma unroll
        for (int nd = 0; nd < 4; ++nd) {
            int s0 = mb + mt * 16 + g;
            int d0 = nd * 8 + 2 * tig;
            *reinterpret_cast<__half2*>(ob + (size_t)s0 * C_DIM + d0)
                = __floats2half2_rn(Oa[mt][nd][0] * inv[mt*2],
                                    Oa[mt][nd][1] * inv[mt*2]);
            *reinterpret_cast<__half2*>(ob + (size_t)(s0 + 8) * C_DIM + d0)
                = __floats2half2_rn(Oa[mt][nd][2] * inv[mt*2 + 1],
                                    Oa[mt][nd][3] * inv[mt*2 + 1]);
        }
}

// ---------------- launch ---------------------------------------------------
extern "C" void kernel_launch(void* const* d_in, const int* in_sizes, int n_in,
                              void* d_out, int out_size)
{
    const float* x_q  = (const float*)d_in[0];
    const float* x_kv = (const float*)d_in[1];
    const float* Wq   = (const float*)d_in[2];
    const float* bq   = (const float*)d_in[3];
    const float* Wk   = (const float*)d_in[4];
    const float* bk   = (const float*)d_in[5];
    const float* Wv   = (const float*)d_in[6];
    const float* bv   = (const float*)d_in[7];
    const float* Wo   = (const float*)d_in[8];
    const float* bo   = (const float*)d_in[9];
    float* out = (float*)d_out;

    cudaFuncSetAttribute(gemm_f16_kernel<0>,
                         cudaFuncAttributeMaxDynamicSharedMemorySize, GEMM_SMEM_CVT);
    cudaFuncSetAttribute(gemm_f16_kernel<1>,
                         cudaFuncAttributeMaxDynamicSharedMemorySize, GEMM_SMEM_CVT);
    cudaFuncSetAttribute(gemm_f16_kernel<2>,
                         cudaFuncAttributeMaxDynamicSharedMemorySize, GEMM_SMEM_CVT);
    cudaFuncSetAttribute(gemm_f16_kernel<3>,
                         cudaFuncAttributeMaxDynamicSharedMemorySize, GEMM_SMEM_DIR);
    cudaFuncSetAttribute(attn_f16_kernel,
                         cudaFuncAttributeMaxDynamicSharedMemorySize, ATT_SMEM);

    __half *wh_base, *x16_base, *attn_base;
    cudaGetSymbolAddress((void**)&wh_base,   g_wh);
    cudaGetSymbolAddress((void**)&x16_base,  g_x16);
    cudaGetSymbolAddress((void**)&attn_base, g_attnh);

    conv_w_kernel<<<256, 256>>>(Wq, Wk, Wv, Wo);
    conv_x16_kernel<<<dim3((BATCH * CHW / 8 + 255) / 256, 2), 256>>>(x_q, x_kv);

    dim3 gq(HW / 128, 2, BATCH);      // (288, 2, 2)
    gemm_f16_kernel<0><<<gq, 128, GEMM_SMEM_CVT>>>(wh_base,                 x16_base,              bq, nullptr);
    gemm_f16_kernel<1><<<gq, 128, GEMM_SMEM_CVT>>>(wh_base +   C_DIM*C_DIM, x16_base + (size_t)BATCH*CHW, bk, nullptr);
    gemm_f16_kernel<2><<<gq, 128, GEMM_SMEM_CVT>>>(wh_base + 2*C_DIM*C_DIM, x16_base + (size_t)BATCH*CHW, bv, nullptr);
    attn_f16_kernel<<<NWH, 256, ATT_SMEM>>>();
    gemm_f16_kernel<3><<<gq, 128, GEMM_SMEM_DIR>>>(wh_base + 3*C_DIM*C_DIM, attn_base,             bo, out);
}

// round 16
// speedup vs baseline: 1.1731x; 1.0266x over previous
#include <cuda_runtime.h>
#include <cuda_fp16.h>
#include <cstdint>

#define C_DIM   256
#define HGT     192
#define WID     192
#define HW      (HGT*WID)
#define CHW     (C_DIM*HW)
#define BATCH   2
#define NWIN    12
#define WINS_B  (NWIN*NWIN)
#define NWINS   (BATCH*WINS_B)      // 288
#define HEADS   8
#define HD      32
#define S_TOK   256
#define NWH     (NWINS*HEADS)       // 2304
// (1/sqrt(32)) * log2(e): q pre-scale so scores are in log2 domain
#define SCALE_Q 0.2550344074444256f

// ---------------- scratch (fp16 intermediates) -------------------------------
__device__ __half g_qh[(size_t)NWH * S_TOK * HD];         // [wh][s][d] (log2-scaled)
__device__ __half g_kh[(size_t)NWH * S_TOK * HD];         // [wh][t][d]
__device__ __half g_vh[(size_t)NWH * HD * S_TOK];         // [wh][d][t]
__device__ __half g_attnh[(size_t)NWINS * S_TOK * C_DIM]; // [win][s][c]
__device__ __half g_wh[4 * C_DIM * C_DIM];                // Wq,Wk,Wv,Wo fp16
__device__ __half g_x16[(size_t)2 * BATCH * CHW];         // x_q ++ x_kv fp16 raster

// ---------------- helpers ----------------------------------------------------
__device__ __forceinline__ void mma_f16(float c[4],
                                        const uint32_t a[4],
                                        const uint32_t b[2]) {
    asm volatile(
        "mma.sync.aligned.m16n8k16.row.col.f32.f16.f16.f32 "
        "{%0,%1,%2,%3},{%4,%5,%6,%7},{%8,%9},{%0,%1,%2,%3};"
        : "+f"(c[0]), "+f"(c[1]), "+f"(c[2]), "+f"(c[3])
        : "r"(a[0]), "r"(a[1]), "r"(a[2]), "r"(a[3]),
          "r"(b[0]), "r"(b[1]));
}

__device__ __forceinline__ void cp_async16(void* smem, const void* gmem) {
    unsigned sa = (unsigned)__cvta_generic_to_shared(smem);
    asm volatile("cp.async.cg.shared.global [%0], [%1], 16;" :: "r"(sa), "l"(gmem));
}
__device__ __forceinline__ void cp_commit() {
    asm volatile("cp.async.commit_group;");
}
template<int N> __device__ __forceinline__ void cp_wait() {
    asm volatile("cp.async.wait_group %0;" :: "n"(N));
}
__device__ __forceinline__ uint32_t ldu32(const __half* p) {
    return *reinterpret_cast<const uint32_t*>(p);
}
__device__ __forceinline__ uint32_t h2u(__half2 h) {
    return *reinterpret_cast<uint32_t*>(&h);
}
__device__ __forceinline__ void ldsm_x2_trans(uint32_t& r0, uint32_t& r1,
                                              uint32_t addr) {
    asm volatile("ldmatrix.sync.aligned.m8n8.x2.trans.shared.b16 {%0,%1}, [%2];"
                 : "=r"(r0), "=r"(r1) : "r"(addr));
}
__device__ __forceinline__ uint32_t ex2_f16x2(uint32_t s) {
    uint32_t p;
    asm("ex2.approx.f16x2 %0, %1;" : "=r"(p) : "r"(s));
    return p;
}

// ---------------- weight conversion ------------------------------------------
__global__ void conv_w_kernel(const float* __restrict__ Wq,
                              const float* __restrict__ Wk,
                              const float* __restrict__ Wv,
                              const float* __restrict__ Wo)
{
    int i = blockIdx.x * blockDim.x + threadIdx.x;
    if (i < C_DIM * C_DIM) {
        g_wh[                 i] = __float2half_rn(Wq[i]);
        g_wh[  C_DIM*C_DIM + i] = __float2half_rn(Wk[i]);
        g_wh[2*C_DIM*C_DIM + i] = __float2half_rn(Wv[i]);
        g_wh[3*C_DIM*C_DIM + i] = __float2half_rn(Wo[i]);
    }
}

// ---------------- x convert: fp32 raster -> fp16 raster (pure streaming) -----
__global__ __launch_bounds__(256)
void conv_x16_kernel(const float* __restrict__ x_q,
                     const float* __restrict__ x_kv)
{
    const size_t i = (size_t)blockIdx.x * 256 + threadIdx.x;  // 8-elem group
    const size_t N8 = (size_t)BATCH * CHW / 8;                // 2,359,296
    if (i >= N8) return;
    const float* src = blockIdx.y ? x_kv : x_q;
    __half* dst = g_x16 + (size_t)blockIdx.y * BATCH * CHW;
    float4 a = reinterpret_cast<const float4*>(src)[2 * i];
    float4 c = reinterpret_cast<const float4*>(src)[2 * i + 1];
    uint4 u;
    u.x = h2u(__floats2half2_rn(a.x, a.y));
    u.y = h2u(__floats2half2_rn(a.z, a.w));
    u.z = h2u(__floats2half2_rn(c.x, c.y));
    u.w = h2u(__floats2half2_rn(c.z, c.w));
    reinterpret_cast<uint4*>(dst)[i] = u;
}

// ---------------- projection GEMM (fp16 mma) ---------------------------------
// out[m,n] = sum_k W[m,k] * X[k,n] + bias[m]
// MODE 0/1/2: B fp16 raster [k][n] from g_x16, frags via ldmatrix.trans.
// MODE 3: B fp16 [n][k] direct from g_attnh (window-token n). Out -> image.
#define G_LD   40
#define G_AB_H (128 * G_LD)                    // 5120 halves per A tile
#define G_BLD  136                             // B [k][n] row: halves (pad 8)
#define G_BS_H (32 * G_BLD)                    // 4352 halves per B tile
#define GEMM_SMEM_CVT ((3*G_AB_H + 3*G_BS_H) * 2)   // 56,832 B
#define GEMM_SMEM_DIR (3*G_AB_H*2 * 2)              // 61,440 B

template<int MODE>
__global__ __launch_bounds__(128, 2)
void gemm_f16_kernel(const __half* __restrict__ Wh,
                     const __half* __restrict__ Xh,
                     const float* __restrict__ bias,
                     float* __restrict__ out_img)
{
    constexpr bool TRN = (MODE < 3);           // B in [k][n], use ldmatrix.trans
    extern __shared__ char smraw[];
    __half* Ah = (__half*)smraw;                          // [3][5120]
    __half* Bs = (__half*)(smraw + 3 * G_AB_H * 2);       // [3][4352] (TRN)
    __half* Bh = (__half*)(smraw + 3 * G_AB_H * 2);       // [3][5120] (DIR)

    const int n0  = blockIdx.x * 128;
    const int m0  = blockIdx.y * 128;
    const int b   = blockIdx.z;
    const int tid  = threadIdx.x;
    const int lane = tid & 31;
    const int warp = tid >> 5;
    const int wm   = warp & 1;
    const int wn   = warp >> 1;
    const int g    = lane >> 2;
    const int tig  = lane & 3;

    const __half* Xb;
    if (TRN) {
        Xb = Xh + (size_t)b * CHW + n0;                   // [k][n] rows, ld=HW
    } else {
        Xb = Xh + ((size_t)(b * WINS_B + (n0 >> 8)) * S_TOK
                   + (n0 & 255)) * (size_t)C_DIM;         // [n][k] rows, ld=C_DIM
    }

    float acc[4][8][4];
    #pragma unroll
    for (int i = 0; i < 4; ++i)
        #pragma unroll
        for (int j = 0; j < 8; ++j)
            #pragma unroll
            for (int r = 0; r < 4; ++r) acc[i][j][r] = 0.f;

    auto load_stage = [&](int kb, int st) {
        const int k0 = kb * 32;
        __half* As = Ah + st * G_AB_H;
        #pragma unroll
        for (int i = 0; i < 4; ++i) {              // A: 128x32 fp16
            int idx = i * 128 + tid;
            int row = idx >> 2, c8 = (idx & 3) << 3;
            cp_async16(As + row * G_LD + c8,
                       Wh + (size_t)(m0 + row) * C_DIM + k0 + c8);
        }
        if (TRN) {
            __half* Bt = Bs + st * G_BS_H;
            #pragma unroll
            for (int i = 0; i < 4; ++i) {          // B: 32k x 128n fp16
                int idx = i * 128 + tid;
                int k = idx >> 4, c8 = (idx & 15) << 3;
                cp_async16(Bt + k * G_BLD + c8,
                           Xb + (size_t)(k0 + k) * HW + c8);
            }
        } else {
            __half* Bd = Bh + st * G_AB_H;
            #pragma unroll
            for (int i = 0; i < 4; ++i) {          // B: 128n x 32k fp16
                int idx = i * 128 + tid;
                int row = idx >> 2, c8 = (idx & 3) << 3;
                cp_async16(Bd + row * G_LD + c8,
                           Xb + (size_t)row * C_DIM + k0 + c8);
            }
        }
        cp_commit();
    };

    load_stage(0, 0);
    load_stage(1, 1);

    const uint32_t bsAddr = (uint32_t)__cvta_generic_to_shared(Bs);
    const int lrow = lane & 15;

    for (int kb = 0; kb < 8; ++kb) {
        const int st = kb % 3;
        if (kb < 7) cp_wait<1>(); else cp_wait<0>();
        __syncthreads();
        if (kb + 2 < 8) load_stage(kb + 2, (kb + 2) % 3);

        const __half* Ab = Ah + st * G_AB_H;
        const uint32_t bRow0 = bsAddr + (st * G_BS_H + lrow * G_BLD) * 2
                             + wn * 64 * 2;       // TRN base (bytes)
        const __half* Bb = Bh + st * G_AB_H;      // DIR base

        #pragma unroll
        for (int ks = 0; ks < 2; ++ks) {
            uint32_t af[4][4];
            #pragma unroll
            for (int fm = 0; fm < 4; ++fm) {
                int rb = wm * 64 + fm * 16;
                const __half* base = Ab + ks * 16 + 2 * tig;
                af[fm][0] = ldu32(base + (rb + g    ) * G_LD);
                af[fm][1] = ldu32(base + (rb + g + 8) * G_LD);
                af[fm][2] = ldu32(base + (rb + g    ) * G_LD + 8);
                af[fm][3] = ldu32(base + (rb + g + 8) * G_LD + 8);
            }
            uint32_t bf[8][2];
            if (TRN) {
                const uint32_t rowA = bRow0 + (ks * 16) * G_BLD * 2;
                #pragma unroll
                for (int fn = 0; fn < 8; ++fn)
                    ldsm_x2_trans(bf[fn][0], bf[fn][1], rowA + fn * 16);
            } else {
                #pragma unroll
                for (int fn = 0; fn < 8; ++fn) {
                    int nb = wn * 64 + fn * 8;
                    const __half* base = Bb + ks * 16 + 2 * tig;
                    bf[fn][0] = ldu32(base + (nb + g) * G_LD);
                    bf[fn][1] = ldu32(base + (nb + g) * G_LD + 8);
                }
            }
            #pragma unroll
            for (int fm = 0; fm < 4; ++fm)
                #pragma unroll
                for (int fn = 0; fn < 8; ++fn)
                    mma_f16(acc[fm][fn], af[fm], bf[fn]);
        }
    }

    // -------- epilogue --------
    if (MODE < 3) {
        // n is raster pixel order -> windowize per element
        const float sc = (MODE == 0) ? SCALE_Q : 1.0f;
        #pragma unroll
        for (int fm = 0; fm < 4; ++fm) {
            int row0 = m0 + wm * 64 + fm * 16 + g;
            int row1 = row0 + 8;
            float b0v = bias[row0], b1v = bias[row1];
            int head0 = row0 >> 5, hd0 = row0 & 31;
            int head1 = row1 >> 5, hd1 = row1 & 31;
            #pragma unroll
            for (int fn = 0; fn < 8; ++fn) {
                int ncol = n0 + wn * 64 + fn * 8 + tig * 2;
                #pragma unroll
                for (int e = 0; e < 2; ++e) {
                    int n   = ncol + e;
                    int h   = n / WID;
                    int w   = n - h * WID;
                    int win = b * WINS_B + (h >> 4) * NWIN + (w >> 4);
                    int s   = ((h & 15) << 4) | (w & 15);
                    __half v0 = __float2half_rn((acc[fm][fn][e]     + b0v) * sc);
                    __half v1 = __float2half_rn((acc[fm][fn][2 + e] + b1v) * sc);
                    if (MODE == 2) {
                        g_vh[((size_t)(win * HEADS + head0) * HD + hd0) * S_TOK + s] = v0;
                        g_vh[((size_t)(win * HEADS + head1) * HD + hd1) * S_TOK + s] = v1;
                    } else {
                        __half* dst = (MODE == 0) ? g_qh : g_kh;
                        dst[((size_t)(win * HEADS + head0) * S_TOK + s) * HD + hd0] = v0;
                        dst[((size_t)(win * HEADS + head1) * S_TOK + s) * HD + hd1] = v1;
                    }
                }
            }
        }
    } else {
        #pragma unroll
        for (int fm = 0; fm < 4; ++fm) {
            int row0 = m0 + wm * 64 + fm * 16 + g;
            int row1 = row0 + 8;
            float b0v = bias[row0], b1v = bias[row1];
            float* o0 = out_img + (size_t)b * CHW + (size_t)row0 * HW;
            float* o1 = out_img + (size_t)b * CHW + (size_t)row1 * HW;
            #pragma unroll
            for (int fn = 0; fn < 8; ++fn) {
                int ncol = n0 + wn * 64 + fn * 8 + tig * 2;
                #pragma unroll
                for (int e = 0; e < 2; ++e) {
                    int n  = ncol + e;
                    int wl = n >> 8;
                    int s  = n & 255;
                    int h  = ((wl / NWIN) << 4) | (s >> 4);
                    int w  = ((wl % NWIN) << 4) | (s & 15);
                    int pix = h * WID + w;
                    o0[pix] = acc[fm][fn][e]     + b0v;
                    o1[pix] = acc[fm][fn][2 + e] + b1v;
                }
            }
        }
    }
}

// ---------------- attention core (fp16 mma; ex2.f16x2 + mma rowsum) ----------
#define AT_LD   40
#define AT_VLD  264
#define ATT_SMEM ((S_TOK*AT_LD + HD*AT_VLD + S_TOK*AT_LD) * 2)   // 57,856 B

__global__ __launch_bounds__(256, 2)
void attn_f16_kernel()
{
    extern __shared__ char smraw[];
    __half* Ksh = (__half*)smraw;                 // [256][40]
    __half* Vsh = Ksh + S_TOK * AT_LD;            // [32][264]
    __half* QP  = Vsh + HD * AT_VLD;              // Q staging, then P

    const int wh   = blockIdx.x;
    const int tid  = threadIdx.x;
    const int lane = tid & 31;
    const int warp = tid >> 5;
    const int g    = lane >> 2;
    const int tig  = lane & 3;

    const __half* qb = g_qh + (size_t)wh * (S_TOK * HD);
    const __half* kb = g_kh + (size_t)wh * (S_TOK * HD);
    const __half* vb = g_vh + (size_t)wh * (HD * S_TOK);

    #pragma unroll
    for (int i = 0; i < 4; ++i) {
        int idx = i * 256 + tid;
        int r   = idx >> 2, c8 = (idx & 3) << 3;
        cp_async16(Ksh + r * AT_LD + c8, kb + r * HD + c8);
        cp_async16(QP  + r * AT_LD + c8, qb + r * HD + c8);
        int d = idx >> 5, cv = (idx & 31) << 3;
        cp_async16(Vsh + d * AT_VLD + cv, vb + d * S_TOK + cv);
    }
    cp_commit();
    cp_wait<0>();
    __syncthreads();

    const int mb = warp * 32;
    uint32_t Qf[2][2][4];
    #pragma unroll
    for (int mt = 0; mt < 2; ++mt)
        #pragma unroll
        for (int ks = 0; ks < 2; ++ks) {
            int rb = mb + mt * 16;
            const __half* base = QP + ks * 16 + 2 * tig;
            Qf[mt][ks][0] = ldu32(base + (rb + g    ) * AT_LD);
            Qf[mt][ks][1] = ldu32(base + (rb + g + 8) * AT_LD);
            Qf[mt][ks][2] = ldu32(base + (rb + g    ) * AT_LD + 8);
            Qf[mt][ks][3] = ldu32(base + (rb + g + 8) * AT_LD + 8);
        }
    __syncthreads();

    __half* Pw = QP + warp * (32 * AT_LD);

    float Oa[2][4][4];
    #pragma unroll
    for (int mt = 0; mt < 2; ++mt)
        #pragma unroll
        for (int nd = 0; nd < 4; ++nd)
            #pragma unroll
            for (int r = 0; r < 4; ++r) Oa[mt][nd][r] = 0.f;
    // rowsum accumulators via ones-mma: Ra[mt][0] = row g, Ra[mt][2] = row g+8
    float Ra[2][4];
    #pragma unroll
    for (int mt = 0; mt < 2; ++mt)
        #pragma unroll
        for (int r = 0; r < 4; ++r) Ra[mt][r] = 0.f;
    const uint32_t ones2[2] = {0x3C003C00u, 0x3C003C00u};   // half2(1,1)

    for (int kt = 0; kt < 8; ++kt) {
        const int t0 = kt * 32;
        float Sa[2][4][4];
        #pragma unroll
        for (int mt = 0; mt < 2; ++mt)
            #pragma unroll
            for (int n = 0; n < 4; ++n)
                #pragma unroll
                for (int r = 0; r < 4; ++r) Sa[mt][n][r] = 0.f;

        #pragma unroll
        for (int ks = 0; ks < 2; ++ks)
            #pragma unroll
            for (int nt = 0; nt < 4; ++nt) {
                const __half* base = Ksh + (t0 + nt * 8 + g) * AT_LD
                                         + ks * 16 + 2 * tig;
                uint32_t bfr[2];
                bfr[0] = ldu32(base);
                bfr[1] = ldu32(base + 8);
                mma_f16(Sa[0][nt], Qf[0][ks], bfr);
                mma_f16(Sa[1][nt], Qf[1][ks], bfr);
            }

        // P = 2^S  (S already in log2 domain): fp16x2 convert + ex2.approx.f16x2
        #pragma unroll
        for (int mt = 0; mt < 2; ++mt)
            #pragma unroll
            for (int nt = 0; nt < 4; ++nt) {
                uint32_t p01 = ex2_f16x2(
                    h2u(__floats2half2_rn(Sa[mt][nt][0], Sa[mt][nt][1])));
                uint32_t p23 = ex2_f16x2(
                    h2u(__floats2half2_rn(Sa[mt][nt][2], Sa[mt][nt][3])));
                *reinterpret_cast<uint32_t*>(
                    Pw + (mt*16 + g    ) * AT_LD + nt*8 + 2*tig) = p01;
                *reinterpret_cast<uint32_t*>(
                    Pw + (mt*16 + g + 8) * AT_LD + nt*8 + 2*tig) = p23;
            }
        __syncwarp();

        #pragma unroll
        for (int ks = 0; ks < 2; ++ks) {
            uint32_t a[2][4];
            #pragma unroll
            for (int mt = 0; mt < 2; ++mt) {
                const __half* base = Pw + ks * 16 + 2 * tig;
                a[mt][0] = ldu32(base + (mt*16 + g    ) * AT_LD);
                a[mt][1] = ldu32(base + (mt*16 + g + 8) * AT_LD);
                a[mt][2] = ldu32(base + (mt*16 + g    ) * AT_LD + 8);
                a[mt][3] = ldu32(base + (mt*16 + g + 8) * AT_LD + 8);
            }
            // rowsum: C = P * ones -> every column holds the row sum
            mma_f16(Ra[0], a[0], ones2);
            mma_f16(Ra[1], a[1], ones2);
            #pragma unroll
            for (int nd = 0; nd < 4; ++nd) {
                const __half* base = Vsh + (nd*8 + g) * AT_VLD
                                         + t0 + ks * 16 + 2 * tig;
                uint32_t bfr[2];
                bfr[0] = ldu32(base);
                bfr[1] = ldu32(base + 8);
                mma_f16(Oa[0][nd], a[0], bfr);
                mma_f16(Oa[1][nd], a[1], bfr);
            }
        }
        __syncwarp();
    }

    float inv[4];
    inv[0] = 1.0f / Ra[0][0];    // row g      (mt=0)
    inv[1] = 1.0f / Ra[0][2];    // row g+8    (mt=0)
    inv[2] = 1.0f / Ra[1][0];    // row g      (mt=1)
    inv[3] = 1.0f / Ra[1][2];    // row g+8    (mt=1)

    const int win  = wh >> 3;
    const int head = wh & 7;
    __half* ob = g_attnh + (size_t)win * (S_TOK * C_DIM) + head * HD;
    #pragma unroll
    for (int mt = 0; mt < 2; ++mt)
        #pragma unroll
        for (int nd = 0; nd < 4; ++nd) {
            int s0 = mb + mt * 16 + g;
            int d0 = nd * 8 + 2 * tig;
            *reinterpret_cast<__half2*>(ob + (size_t)s0 * C_DIM + d0)
                = __floats2half2_rn(Oa[mt][nd][0] * inv[mt*2],
                                    Oa[mt][nd][1] * inv[mt*2]);
            *reinterpret_cast<__half2*>(ob + (size_t)(s0 + 8) * C_DIM + d0)
                = __floats2half2_rn(Oa[mt][nd][2] * inv[mt*2 + 1],
                                    Oa[mt][nd][3] * inv[mt*2 + 1]);
        }
}

// ---------------- launch ---------------------------------------------------
extern "C" void kernel_launch(void* const* d_in, const int* in_sizes, int n_in,
                              void* d_out, int out_size)
{
    const float* x_q  = (const float*)d_in[0];
    const float* x_kv = (const float*)d_in[1];
    const float* Wq   = (const float*)d_in[2];
    const float* bq   = (const float*)d_in[3];
    const float* Wk   = (const float*)d_in[4];
    const float* bk   = (const float*)d_in[5];
    const float* Wv   = (const float*)d_in[6];
    const float* bv   = (const float*)d_in[7];
    const float* Wo   = (const float*)d_in[8];
    const float* bo   = (const float*)d_in[9];
    float* out = (float*)d_out;

    cudaFuncSetAttribute(gemm_f16_kernel<0>,
                         cudaFuncAttributeMaxDynamicSharedMemorySize, GEMM_SMEM_CVT);
    cudaFuncSetAttribute(gemm_f16_kernel<1>,
                         cudaFuncAttributeMaxDynamicSharedMemorySize, GEMM_SMEM_CVT);
    cudaFuncSetAttribute(gemm_f16_kernel<2>,
                         cudaFuncAttributeMaxDynamicSharedMemorySize, GEMM_SMEM_CVT);
    cudaFuncSetAttribute(gemm_f16_kernel<3>,
                         cudaFuncAttributeMaxDynamicSharedMemorySize, GEMM_SMEM_DIR);
    cudaFuncSetAttribute(attn_f16_kernel,
                         cudaFuncAttributeMaxDynamicSharedMemorySize, ATT_SMEM);

    __half *wh_base, *x16_base, *attn_base;
    cudaGetSymbolAddress((void**)&wh_base,   g_wh);
    cudaGetSymbolAddress((void**)&x16_base,  g_x16);
    cudaGetSymbolAddress((void**)&attn_base, g_attnh);

    conv_w_kernel<<<256, 256>>>(Wq, Wk, Wv, Wo);
    conv_x16_kernel<<<dim3((BATCH * CHW / 8 + 255) / 256, 2), 256>>>(x_q, x_kv);

    dim3 gq(HW / 128, 2, BATCH);      // (288, 2, 2)
    gemm_f16_kernel<0><<<gq, 128, GEMM_SMEM_CVT>>>(wh_base,                 x16_base,              bq, nullptr);
    gemm_f16_kernel<1><<<gq, 128, GEMM_SMEM_CVT>>>(wh_base +   C_DIM*C_DIM, x16_base + (size_t)BATCH*CHW, bk, nullptr);
    gemm_f16_kernel<2><<<gq, 128, GEMM_SMEM_CVT>>>(wh_base + 2*C_DIM*C_DIM, x16_base + (size_t)BATCH*CHW, bv, nullptr);
    attn_f16_kernel<<<NWH, 256, ATT_SMEM>>>();
    gemm_f16_kernel<3><<<gq, 128, GEMM_SMEM_DIR>>>(wh_base + 3*C_DIM*C_DIM, attn_base,             bo, out);
}